// round 2
// baseline (speedup 1.0000x reference)
#include <cuda_runtime.h>

// Problem constants
#define NB 16
#define NC 3
#define H 768
#define W 768
#define HS 48            // H/16
#define WS 48            // W/16
#define NPIX (HS * WS)   // 2304
#define RADIUS 8

// Downsampled features: (f0, f1, f2, |f|^2) per (b, i). 16*2304*16B = 576 KB scratch.
__device__ float4 g_feats[NB * NPIX];

// ---------------------------------------------------------------------------
// Kernel 1: 16x bilinear downsample. Half-pixel centers => src = 16*i + 7.5,
// exact 0.5/0.5 weights => average of the 2x2 pixel block at (16y+7, 16x+7).
// ---------------------------------------------------------------------------
__global__ void resize_feats_kernel(const float* __restrict__ img) {
    int t = blockIdx.x * blockDim.x + threadIdx.x;
    if (t >= NB * NPIX) return;
    int b = t / NPIX;
    int i = t - b * NPIX;
    int yi = i / WS;
    int xi = i - yi * WS;
    int y0 = yi * 16 + 7;
    int x0 = xi * 16 + 7;

    float f[3];
#pragma unroll
    for (int c = 0; c < 3; ++c) {
        const float* p = img + ((size_t)(b * NC + c) * H + y0) * W + x0;
        // match separable resize: average rows first, then columns
        float r0 = 0.5f * (p[0] + p[1]);
        float r1 = 0.5f * (p[W] + p[W + 1]);
        f[c] = 0.5f * (r0 + r1);
    }
    float sq = f[0] * f[0] + f[1] * f[1] + f[2] * f[2];
    g_feats[t] = make_float4(f[0], f[1], f[2], sq);
}

// ---------------------------------------------------------------------------
// Kernel 2: affinity. One thread writes 16 consecutive floats (4 x float4).
// A row (2304 floats) = 144 chunks of 16; since 48 % 16 == 0 a chunk never
// crosses a yj row -> ONE dy test per 64 output bytes. Block = 288 threads
// covering two output rows (2 x 144). ~65% of chunks fail the dy test and
// reduce to 4 zero STG.128s, amortizing all index ALU 4x vs the previous
// 1-float4-per-thread version.
// ---------------------------------------------------------------------------
__global__ void __launch_bounds__(288) affinity_kernel(float4* __restrict__ out) {
    const int tid = threadIdx.x;
    const int r   = (tid >= 144) ? 1 : 0;
    const int c   = tid - r * 144;            // chunk index within row, 0..143
    const int i   = blockIdx.x * 2 + r;       // output row, 0..2303
    const int b   = blockIdx.y;               // batch, 0..15

    const int yj  = c / 3;                    // chunk's (single) j-grid row
    const int xj0 = (c - yj * 3) * 16;        // first x within chunk
    const int yi  = i / WS;
    const int xi  = i - yi * WS;

    float4* __restrict__ orow =
        out + ((size_t)b * NPIX + i) * (NPIX / 4) + c * 4;

    const int dy = yi - yj;
    if (dy < -RADIUS || dy > RADIUS) {
        const float4 z = make_float4(0.f, 0.f, 0.f, 0.f);
        orow[0] = z; orow[1] = z; orow[2] = z; orow[3] = z;
        return;
    }

    const float4* __restrict__ frow = g_feats + b * NPIX;
    const float4 fi  = frow[i];
    const float  sdy = (float)(dy * dy);

    float v[16];
#pragma unroll
    for (int k = 0; k < 16; ++k) {
        const int dx = xi - (xj0 + k);
        float val = 0.f;
        if (dx >= -RADIUS && dx <= RADIUS) {
            const float4 fj = frow[c * 16 + k];   // flat j = yj*48 + xj0 + k
            float cd = fi.w + fj.w
                     - 2.0f * (fi.x * fj.x + fi.y * fj.y + fi.z * fj.z);
            cd = fmaxf(cd, 0.0f);
            val = __expf(-(50.0f * cd + 0.02f * (sdy + (float)(dx * dx))));
        }
        v[k] = val;
    }

#pragma unroll
    for (int q = 0; q < 4; ++q)
        orow[q] = make_float4(v[4 * q], v[4 * q + 1], v[4 * q + 2], v[4 * q + 3]);
}

// ---------------------------------------------------------------------------
extern "C" void kernel_launch(void* const* d_in, const int* in_sizes, int n_in,
                              void* d_out, int out_size) {
    const float* img = (const float*)d_in[0];
    float4* out = (float4*)d_out;

    const int nfeat = NB * NPIX;
    resize_feats_kernel<<<(nfeat + 255) / 256, 256>>>(img);

    dim3 grid(NPIX / 2, NB);       // (1152, 16), 288 threads = 2 rows/block
    affinity_kernel<<<grid, 288>>>(out);
}

// round 3
// speedup vs baseline: 1.3293x; 1.3293x over previous
#include <cuda_runtime.h>

// Problem constants
#define NB 16
#define NC 3
#define H 768
#define W 768
#define HS 48            // H/16
#define WS 48            // W/16
#define NPIX (HS * WS)   // 2304
#define RADIUS 8

// Downsampled features: (f0, f1, f2, |f|^2) per (b, i). 16*2304*16B = 576 KB scratch.
__device__ float4 g_feats[NB * NPIX];

// ---------------------------------------------------------------------------
// Kernel 1: 16x bilinear downsample. Half-pixel centers => src = 16*i + 7.5,
// exact 0.5/0.5 weights => average of the 2x2 pixel block at (16y+7, 16x+7).
// ---------------------------------------------------------------------------
__global__ void resize_feats_kernel(const float* __restrict__ img) {
    int t = blockIdx.x * blockDim.x + threadIdx.x;
    if (t >= NB * NPIX) return;
    int b = t / NPIX;
    int i = t - b * NPIX;
    int yi = i / WS;
    int xi = i - yi * WS;
    int y0 = yi * 16 + 7;
    int x0 = xi * 16 + 7;

    float f[3];
#pragma unroll
    for (int c = 0; c < 3; ++c) {
        const float* p = img + ((size_t)(b * NC + c) * H + y0) * W + x0;
        // match separable resize: average rows first, then columns
        float r0 = 0.5f * (p[0] + p[1]);
        float r1 = 0.5f * (p[W] + p[W + 1]);
        f[c] = 0.5f * (r0 + r1);
    }
    float sq = f[0] * f[0] + f[1] * f[1] + f[2] * f[2];
    g_feats[t] = make_float4(f[0], f[1], f[2], sq);
}

// ---------------------------------------------------------------------------
// Kernel 2: affinity. One block = one output row i (2304 floats).
// 288 threads, thread t owns 8 CONSECUTIVE floats (32 B) -> one 256-bit store,
// lane-consecutive addresses => a warp writes 1024 contiguous bytes (fully
// coalesced). 48 % 8 == 0 so a chunk has a single yj => one dy test per 32 B;
// ~65% of threads take the pure zero-store path.
// ---------------------------------------------------------------------------
__global__ void __launch_bounds__(288) affinity_kernel(float* __restrict__ out) {
    const int t = threadIdx.x;                 // chunk index, 0..287
    const int i = blockIdx.x;                  // output row, 0..2303
    const int b = blockIdx.y;                  // batch, 0..15

    const int yj  = t / 6;                     // chunk's (single) j-grid row
    const int xj0 = (t - yj * 6) * 8;          // first x within chunk
    const int yi  = i / WS;
    const int xi  = i - yi * WS;

    float* optr = out + ((size_t)b * NPIX + i) * NPIX + t * 8;

    float v0 = 0.f, v1 = 0.f, v2 = 0.f, v3 = 0.f;
    float v4 = 0.f, v5 = 0.f, v6 = 0.f, v7 = 0.f;

    const int dy = yi - yj;
    if (dy >= -RADIUS && dy <= RADIUS) {
        const float4* __restrict__ frow = g_feats + b * NPIX;
        const float4 fi  = frow[i];
        const float  sdy = (float)(dy * dy);
        float v[8];
#pragma unroll
        for (int k = 0; k < 8; ++k) {
            const int dx = xi - (xj0 + k);
            float val = 0.f;
            if (dx >= -RADIUS && dx <= RADIUS) {
                const float4 fj = frow[t * 8 + k];   // flat j = yj*48 + xj0 + k
                float cd = fi.w + fj.w
                         - 2.0f * (fi.x * fj.x + fi.y * fj.y + fi.z * fj.z);
                cd = fmaxf(cd, 0.0f);
                val = __expf(-(50.0f * cd + 0.02f * (sdy + (float)(dx * dx))));
            }
            v[k] = val;
        }
        v0 = v[0]; v1 = v[1]; v2 = v[2]; v3 = v[3];
        v4 = v[4]; v5 = v[5]; v6 = v[6]; v7 = v[7];
    }

    // 256-bit store (sm_100+): one STG.256 per thread, 32B aligned.
    asm volatile(
        "st.global.v8.f32 [%0], {%1, %2, %3, %4, %5, %6, %7, %8};"
        :: "l"(optr),
           "f"(v0), "f"(v1), "f"(v2), "f"(v3),
           "f"(v4), "f"(v5), "f"(v6), "f"(v7)
        : "memory");
}

// ---------------------------------------------------------------------------
extern "C" void kernel_launch(void* const* d_in, const int* in_sizes, int n_in,
                              void* d_out, int out_size) {
    const float* img = (const float*)d_in[0];
    float* out = (float*)d_out;

    const int nfeat = NB * NPIX;
    resize_feats_kernel<<<(nfeat + 255) / 256, 256>>>(img);

    dim3 grid(NPIX, NB);           // one block per (row, batch)
    affinity_kernel<<<grid, 288>>>(out);
}

// round 5
// speedup vs baseline: 1.8595x; 1.3988x over previous
#include <cuda_runtime.h>

// Problem constants
#define NB 16
#define NC 3
#define H 768
#define W 768
#define HS 48            // H/16
#define WS 48            // W/16
#define NPIX (HS * WS)   // 2304
#define RADIUS 8

// Downsampled features: (f0, f1, f2, |f|^2) per (b, i). 16*2304*16B = 576 KB scratch.
__device__ float4 g_feats[NB * NPIX];

// ---------------------------------------------------------------------------
// Kernel 1: 16x bilinear downsample. Half-pixel centers => src = 16*i + 7.5,
// exact 0.5/0.5 weights => average of the 2x2 pixel block at (16y+7, 16x+7).
// Scalar loads only: x0 = 16*xi + 7 is ODD, so vector loads would misalign.
// ---------------------------------------------------------------------------
__global__ void resize_feats_kernel(const float* __restrict__ img) {
    int t = blockIdx.x * blockDim.x + threadIdx.x;
    if (t >= NB * NPIX) return;
    int b = t / NPIX;
    int i = t - b * NPIX;
    int yi = i / WS;
    int xi = i - yi * WS;
    int y0 = yi * 16 + 7;
    int x0 = xi * 16 + 7;

    float f[3];
#pragma unroll
    for (int c = 0; c < 3; ++c) {
        const float* p = img + ((size_t)(b * NC + c) * H + y0) * W + x0;
        // match separable resize: average rows first, then columns
        float r0 = 0.5f * (p[0] + p[1]);
        float r1 = 0.5f * (p[W] + p[W + 1]);
        f[c] = 0.5f * (r0 + r1);
    }
    float sq = f[0] * f[0] + f[1] * f[1] + f[2] * f[2];
    g_feats[t] = make_float4(f[0], f[1], f[2], sq);
}

// ---------------------------------------------------------------------------
// Kernel 2: affinity, row-loop form.
// Grid (144, 16): block bx handles rows i = bx, bx+144, ..., bx+15*144 of
// batch by. Stride 144 == 3*WS, so xi is CONSTANT for the whole block and
// each thread's 4 j-columns (fj values, dx mask, dx^2) are block-lifetime
// invariants loaded/computed once. Inner loop per row: dy += 3, band test,
// broadcast fi load, <=4 exp, one streaming STG.128. 576 threads = one
// float4 (4 consecutive j) per thread; warp writes 512 contiguous bytes.
// ---------------------------------------------------------------------------
__global__ void __launch_bounds__(576) affinity_kernel(float* __restrict__ out) {
    const int q  = threadIdx.x;            // float4 index within row, 0..575
    const int bx = blockIdx.x;             // 0..143
    const int b  = blockIdx.y;             // 0..15

    const int j0  = q * 4;
    const int yj  = q / 12;                // shared by the 4 j's (4 | 48)
    const int xj0 = j0 - yj * WS;
    const int xi  = bx - (bx / WS) * WS;   // constant across all 16 rows

    const float4* __restrict__ frow = g_feats + b * NPIX;

    // Block-lifetime invariants: fj's, dx mask, spatial dx^2 term.
    float4 fj[4];
    float  sdx[4];
    bool   ok[4];
#pragma unroll
    for (int k = 0; k < 4; ++k) {
        const int dx = xi - (xj0 + k);
        ok[k]  = (dx >= -RADIUS) && (dx <= RADIUS);
        sdx[k] = (float)(dx * dx);
        fj[k]  = frow[j0 + k];
    }

    int yi = bx / WS;                      // row 0's grid-y; +3 per iteration
    const float4 zero = make_float4(0.f, 0.f, 0.f, 0.f);
    float4* optr = (float4*)(out + (((size_t)b * NPIX + bx) * NPIX)) + q;
    const size_t ostride = (size_t)144 * (NPIX / 4);   // float4s per 144 rows

    int i = bx;
#pragma unroll 4
    for (int it = 0; it < 16; ++it) {
        const int dy = yi - yj;
        float4 v = zero;
        if (dy >= -RADIUS && dy <= RADIUS) {
            const float4 fi  = frow[i];
            const float  sdy = (float)(dy * dy);
            float* vv = (float*)&v;
#pragma unroll
            for (int k = 0; k < 4; ++k) {
                if (ok[k]) {
                    float cd = fi.w + fj[k].w
                             - 2.0f * (fi.x * fj[k].x + fi.y * fj[k].y + fi.z * fj[k].z);
                    cd = fmaxf(cd, 0.0f);
                    vv[k] = __expf(-(50.0f * cd + 0.02f * (sdy + sdx[k])));
                }
            }
        }
        __stcs(optr, v);                   // streaming 128-bit store
        optr += ostride;
        i  += 144;
        yi += 3;
    }
}

// ---------------------------------------------------------------------------
extern "C" void kernel_launch(void* const* d_in, const int* in_sizes, int n_in,
                              void* d_out, int out_size) {
    const float* img = (const float*)d_in[0];
    float* out = (float*)d_out;

    const int nfeat = NB * NPIX;
    resize_feats_kernel<<<(nfeat + 255) / 256, 256>>>(img);

    dim3 grid(144, NB);                    // 2304 blocks, 16 rows each
    affinity_kernel<<<grid, 576>>>(out);
}